// round 5
// baseline (speedup 1.0000x reference)
#include <cuda_runtime.h>
#include <math.h>

// Problem constants (fixed shapes from reference)
#define B_    32
#define C_    256
#define H_    64
#define W_    64
#define HW_   (H_ * W_)          // 4096
#define BHW_  (B_ * HW_)         // 131072
#define EPS_  1e-8f

#define THREADS_      256        // 32 positions x 8 channel-eighths per tile
#define POS_PER_TILE_ 32
#define NOCT_         8
#define CO_           (C_ / NOCT_)            // 32 channels per thread per tile
#define NTILES_       (BHW_ / POS_PER_TILE_)  // 4096
#define NBLOCKS_      1024                    // each CTA does exactly 4 tiles
#define TILES_PER_CTA_ (NTILES_ / NBLOCKS_)   // 4

// Scratch accumulators: [0] = sum(sim*mask), [1] = sum(mask).
// Zero-initialized at module load; the finalizing block resets them after
// each use so every graph replay sees identical initial state.
__device__ float    g_acc[2];
__device__ unsigned g_count;

__global__ __launch_bounds__(THREADS_)
void cms_fused_kernel(const float* __restrict__ u,
                      const float* __restrict__ m,
                      const int*   __restrict__ mask,
                      float*       __restrict__ out) {
    const int pos_in_tile = threadIdx.x & (POS_PER_TILE_ - 1);  // 0..31
    const int oct         = threadIdx.x >> 5;                   // 0..7 (== warp id)

    __shared__ float s_dot[NOCT_ - 1][POS_PER_TILE_];
    __shared__ float s_uu [NOCT_ - 1][POS_PER_TILE_];
    __shared__ float s_mm [NOCT_ - 1][POS_PER_TILE_];
    __shared__ float s_red[2][NOCT_];
    __shared__ bool  s_last;

    float contrib = 0.0f, msum = 0.0f;   // accumulated across tiles

    #pragma unroll 1
    for (int t = 0; t < TILES_PER_CTA_; ++t) {
        const int tile = blockIdx.x + t * NBLOCKS_;          // 0..4095
        const int pos  = tile * POS_PER_TILE_ + pos_in_tile; // 0..131071
        const int b    = pos >> 12;            // / HW_
        const int hw   = pos & (HW_ - 1);      // % HW_

        // This thread covers channels [oct*32, oct*32+32) of position (b,hw).
        const size_t base = (size_t)b * C_ * HW_ + (size_t)oct * CO_ * HW_ + hw;
        const float* __restrict__ up = u + base;
        const float* __restrict__ mp = m + base;

        float dot = 0.0f, uu = 0.0f, mm = 0.0f;
        #pragma unroll 8
        for (int c = 0; c < CO_; ++c) {
            const float a = __ldcs(up + (size_t)c * HW_);
            const float x = __ldcs(mp + (size_t)c * HW_);
            dot = fmaf(a, x, dot);
            uu  = fmaf(a, a, uu);
            mm  = fmaf(x, x, mm);
        }

        // Combine the 8 channel-eighths of each position through shared memory.
        if (oct != 0) {
            s_dot[oct - 1][pos_in_tile] = dot;
            s_uu [oct - 1][pos_in_tile] = uu;
            s_mm [oct - 1][pos_in_tile] = mm;
        }
        __syncthreads();

        if (oct == 0) {
            #pragma unroll
            for (int q = 0; q < NOCT_ - 1; ++q) {
                dot += s_dot[q][pos_in_tile];
                uu  += s_uu [q][pos_in_tile];
                mm  += s_mm [q][pos_in_tile];
            }
            const float mf = (__ldg(mask + pos) != 0) ? 1.0f : 0.0f;
            const float denom = fmaxf(sqrtf(uu), EPS_) * fmaxf(sqrtf(mm), EPS_);
            contrib += (dot / denom) * mf;
            msum    += mf;
        }
        __syncthreads();   // smem reuse safety for the next tile
    }

    // Only warp 0 (oct==0) holds nonzero contributions.
    #pragma unroll
    for (int off = 16; off > 0; off >>= 1) {
        contrib += __shfl_down_sync(0xFFFFFFFFu, contrib, off);
        msum    += __shfl_down_sync(0xFFFFFFFFu, msum, off);
    }

    const int lane = threadIdx.x & 31;
    if (oct == 0 && lane == 0) {
        atomicAdd(&g_acc[0], contrib);
        atomicAdd(&g_acc[1], msum);
        __threadfence();
        const unsigned old = atomicAdd(&g_count, 1u);
        s_last = (old == (unsigned)(gridDim.x - 1));
    }
    __syncthreads();

    // Last block: produce output and reset state for the next replay.
    if (s_last && threadIdx.x == 0) {
        out[0] = g_acc[0] / g_acc[1];
        g_acc[0] = 0.0f;
        g_acc[1] = 0.0f;
        g_count  = 0u;
    }
}

extern "C" void kernel_launch(void* const* d_in, const int* in_sizes, int n_in,
                              void* d_out, int out_size) {
    const float* u    = (const float*)d_in[0];  // unmasked_latent_tensors [B,C,H,W]
    const float* m    = (const float*)d_in[1];  // masked_latent_tensors   [B,C,H,W]
    const int*   mask = (const int*)d_in[2];    // latent_mask [B,H,W]
    float* out = (float*)d_out;

    cms_fused_kernel<<<NBLOCKS_, THREADS_>>>(u, m, mask, out);
}

// round 6
// speedup vs baseline: 1.0412x; 1.0412x over previous
#include <cuda_runtime.h>
#include <math.h>

// Problem constants (fixed shapes from reference)
#define B_    32
#define C_    256
#define H_    64
#define W_    64
#define HW_   (H_ * W_)          // 4096
#define BHW_  (B_ * HW_)         // 131072
#define EPS_  1e-8f

#define THREADS_      128        // 32 positions x 4 channel-quarters
#define POS_PER_BLK_  32
#define NBLOCKS_      (BHW_ / POS_PER_BLK_)   // 4096
#define NQUART_       4
#define CQ_           (C_ / NQUART_)          // 64 channels per thread

// Scratch accumulators: [0] = sum(sim*mask), [1] = sum(mask).
// Zero-initialized at module load; the finalizing block resets them after
// each use so every graph replay sees identical initial state.
__device__ float    g_acc[2];
__device__ unsigned g_count;

__global__ __launch_bounds__(THREADS_)
void cms_fused_kernel(const float* __restrict__ u,
                      const float* __restrict__ m,
                      const int*   __restrict__ mask,
                      float*       __restrict__ out) {
    const int pos_in_blk = threadIdx.x & (POS_PER_BLK_ - 1);  // 0..31 (== lane)
    const int quart      = threadIdx.x >> 5;                  // 0..3  (== warp)
    const int pos        = blockIdx.x * POS_PER_BLK_ + pos_in_blk; // 0..131071

    const int b  = pos >> 12;            // / HW_
    const int hw = pos & (HW_ - 1);      // % HW_

    // This thread covers channels [quart*64, quart*64+64) of position (b,hw).
    const size_t base = (size_t)b * C_ * HW_ + (size_t)quart * CQ_ * HW_ + hw;
    const float* __restrict__ up = u + base;
    const float* __restrict__ mp = m + base;

    float dot = 0.0f, uu = 0.0f, mm = 0.0f;
    #pragma unroll 8
    for (int c = 0; c < CQ_; ++c) {
        const float a = __ldcs(up + (size_t)c * HW_);
        const float x = __ldcs(mp + (size_t)c * HW_);
        dot = fmaf(a, x, dot);
        uu  = fmaf(a, a, uu);
        mm  = fmaf(x, x, mm);
    }

    // Combine the four channel-quarters of each position through shared memory.
    __shared__ float s_dot[NQUART_ - 1][POS_PER_BLK_];
    __shared__ float s_uu [NQUART_ - 1][POS_PER_BLK_];
    __shared__ float s_mm [NQUART_ - 1][POS_PER_BLK_];
    __shared__ bool  s_last;

    if (quart != 0) {
        s_dot[quart - 1][pos_in_blk] = dot;
        s_uu [quart - 1][pos_in_blk] = uu;
        s_mm [quart - 1][pos_in_blk] = mm;
    }
    __syncthreads();

    // Warp 0 (quart==0) holds one position per lane; finish it there.
    if (quart == 0) {
        #pragma unroll
        for (int q = 0; q < NQUART_ - 1; ++q) {
            dot += s_dot[q][pos_in_blk];
            uu  += s_uu [q][pos_in_blk];
            mm  += s_mm [q][pos_in_blk];
        }
        const float mf = (__ldg(mask + pos) != 0) ? 1.0f : 0.0f;
        const float denom = fmaxf(sqrtf(uu), EPS_) * fmaxf(sqrtf(mm), EPS_);
        float contrib = (dot / denom) * mf;
        float msum    = mf;

        // Warp reduction over the 32 positions of this block.
        #pragma unroll
        for (int off = 16; off > 0; off >>= 1) {
            contrib += __shfl_down_sync(0xFFFFFFFFu, contrib, off);
            msum    += __shfl_down_sync(0xFFFFFFFFu, msum, off);
        }

        if (pos_in_blk == 0) {
            atomicAdd(&g_acc[0], contrib);
            atomicAdd(&g_acc[1], msum);
            __threadfence();
            const unsigned old = atomicAdd(&g_count, 1u);
            s_last = (old == (unsigned)(gridDim.x - 1));
        }
    }
    __syncthreads();

    // Last block: produce output and reset state for the next replay.
    if (s_last && threadIdx.x == 0) {
        out[0] = g_acc[0] / g_acc[1];
        g_acc[0] = 0.0f;
        g_acc[1] = 0.0f;
        g_count  = 0u;
    }
}

extern "C" void kernel_launch(void* const* d_in, const int* in_sizes, int n_in,
                              void* d_out, int out_size) {
    const float* u    = (const float*)d_in[0];  // unmasked_latent_tensors [B,C,H,W]
    const float* m    = (const float*)d_in[1];  // masked_latent_tensors   [B,C,H,W]
    const int*   mask = (const int*)d_in[2];    // latent_mask [B,H,W]
    float* out = (float*)d_out;

    cms_fused_kernel<<<NBLOCKS_, THREADS_>>>(u, m, mask, out);
}

// round 7
// speedup vs baseline: 1.0809x; 1.0381x over previous
#include <cuda_runtime.h>
#include <math.h>
#include <cstdint>

// Problem constants (fixed shapes from reference)
#define B_    32
#define C_    256
#define HW_   4096
#define BHW_  131072
#define EPS_  1e-8f

#define POS_PER_CTA_ 512
#define NCTAS_       (BHW_ / POS_PER_CTA_)   // 256
#define NSTAGES_     8
#define NCONS_       256                     // consumer threads (8 warps)
#define THREADS_     288                     // +1 producer warp
#define TILE_BYTES_  (POS_PER_CTA_ * 4)      // 2048 B per tensor per stage
#define STAGE_TX_    (2 * TILE_BYTES_)       // 4096 B per stage

// Scratch accumulators: [0] = sum(sim*mask), [1] = sum(mask).
// Zero-initialized at module load; the finalizing block resets them after
// each use so every graph replay sees identical initial state.
__device__ float    g_acc[2];
__device__ unsigned g_count;

__device__ __forceinline__ uint32_t smem_u32(const void* p) {
    uint32_t a;
    asm("{ .reg .u64 t; cvta.to.shared.u64 t, %1; cvt.u32.u64 %0, t; }"
        : "=r"(a) : "l"(p));
    return a;
}
__device__ __forceinline__ void mbar_init(uint32_t m, uint32_t cnt) {
    asm volatile("mbarrier.init.shared.b64 [%0], %1;" :: "r"(m), "r"(cnt) : "memory");
}
__device__ __forceinline__ void mbar_expect_tx(uint32_t m, uint32_t tx) {
    asm volatile("mbarrier.arrive.expect_tx.shared.b64 _, [%0], %1;"
                 :: "r"(m), "r"(tx) : "memory");
}
__device__ __forceinline__ void mbar_arrive(uint32_t m) {
    asm volatile("mbarrier.arrive.shared.b64 _, [%0];" :: "r"(m) : "memory");
}
__device__ __forceinline__ void mbar_wait(uint32_t m, uint32_t parity) {
    asm volatile(
        "{\n\t"
        ".reg .pred P;\n\t"
        "WL_%=:\n\t"
        "mbarrier.try_wait.parity.acquire.cta.shared::cta.b64 P, [%0], %1, 0x989680;\n\t"
        "@P bra.uni WD_%=;\n\t"
        "bra.uni WL_%=;\n\t"
        "WD_%=:\n\t"
        "}"
        :: "r"(m), "r"(parity) : "memory");
}
__device__ __forceinline__ void bulk_g2s(uint32_t dst, const void* src,
                                         uint32_t bytes, uint32_t mbar) {
    asm volatile(
        "cp.async.bulk.shared::cta.global.mbarrier::complete_tx::bytes "
        "[%0], [%1], %2, [%3];"
        :: "r"(dst), "l"(src), "r"(bytes), "r"(mbar) : "memory");
}

__global__ __launch_bounds__(THREADS_)
void cms_tma_kernel(const float* __restrict__ u,
                    const float* __restrict__ m,
                    const int*   __restrict__ mask,
                    float*       __restrict__ out) {
    __shared__ alignas(128) float su[NSTAGES_][POS_PER_CTA_];   // 16 KB
    __shared__ alignas(128) float sv[NSTAGES_][POS_PER_CTA_];   // 16 KB
    __shared__ alignas(8)  unsigned long long bar_full[NSTAGES_];
    __shared__ alignas(8)  unsigned long long bar_empty[NSTAGES_];
    __shared__ float s_c[8], s_m[8];
    __shared__ bool  s_last;

    const int tid = threadIdx.x;
    const int cta = blockIdx.x;
    const int b   = cta >> 3;                       // 8 CTAs per batch image
    const int hw0 = (cta & 7) * POS_PER_CTA_;

    const uint32_t full0  = smem_u32(&bar_full[0]);
    const uint32_t empty0 = smem_u32(&bar_empty[0]);

    if (tid == 0) {
        #pragma unroll
        for (int s = 0; s < NSTAGES_; ++s) {
            mbar_init(full0  + 8u * s, 1);       // producer's expect_tx arrive
            mbar_init(empty0 + 8u * s, NCONS_);  // all consumers arrive
        }
    }
    __syncthreads();

    float contrib = 0.0f, msum = 0.0f;

    if (tid >= NCONS_) {
        // ---------------- producer (single thread of warp 8) ----------------
        if (tid == NCONS_) {
            const char* gu = (const char*)(u + (size_t)b * C_ * HW_ + hw0);
            const char* gm = (const char*)(m + (size_t)b * C_ * HW_ + hw0);
            const uint32_t du = smem_u32(&su[0][0]);
            const uint32_t dv = smem_u32(&sv[0][0]);
            int st = 0, ph = 1;   // phase 1: first NSTAGES_ empty-waits pass immediately
            for (int c = 0; c < C_; ++c) {
                const uint32_t fb = full0 + 8u * st;
                mbar_wait(empty0 + 8u * st, (uint32_t)ph);
                mbar_expect_tx(fb, STAGE_TX_);
                bulk_g2s(du + (uint32_t)st * TILE_BYTES_, gu + (size_t)c * HW_ * 4,
                         TILE_BYTES_, fb);
                bulk_g2s(dv + (uint32_t)st * TILE_BYTES_, gm + (size_t)c * HW_ * 4,
                         TILE_BYTES_, fb);
                if (++st == NSTAGES_) { st = 0; ph ^= 1; }
            }
        }
    } else {
        // ---------------- consumers: thread t owns positions hw0+2t, hw0+2t+1
        float dot0 = 0.0f, uu0 = 0.0f, mm0 = 0.0f;
        float dot1 = 0.0f, uu1 = 0.0f, mm1 = 0.0f;
        const float2* pu = (const float2*)&su[0][0];
        const float2* pv = (const float2*)&sv[0][0];
        int st = 0, ph = 0;
        for (int c = 0; c < C_; ++c) {
            mbar_wait(full0 + 8u * st, (uint32_t)ph);
            const float2 a = pu[st * (POS_PER_CTA_ / 2) + tid];
            const float2 x = pv[st * (POS_PER_CTA_ / 2) + tid];
            dot0 = fmaf(a.x, x.x, dot0);
            uu0  = fmaf(a.x, a.x, uu0);
            mm0  = fmaf(x.x, x.x, mm0);
            dot1 = fmaf(a.y, x.y, dot1);
            uu1  = fmaf(a.y, a.y, uu1);
            mm1  = fmaf(x.y, x.y, mm1);
            mbar_arrive(empty0 + 8u * st);
            if (++st == NSTAGES_) { st = 0; ph ^= 1; }
        }

        const int pos = b * HW_ + hw0 + 2 * tid;
        const int2 mk = *(const int2*)(mask + pos);
        const float mf0 = (mk.x != 0) ? 1.0f : 0.0f;
        const float mf1 = (mk.y != 0) ? 1.0f : 0.0f;
        const float d0 = fmaxf(sqrtf(uu0), EPS_) * fmaxf(sqrtf(mm0), EPS_);
        const float d1 = fmaxf(sqrtf(uu1), EPS_) * fmaxf(sqrtf(mm1), EPS_);
        contrib = (dot0 / d0) * mf0 + (dot1 / d1) * mf1;
        msum    = mf0 + mf1;
    }

    // Warp reduction (producer warp contributes zeros)
    #pragma unroll
    for (int off = 16; off > 0; off >>= 1) {
        contrib += __shfl_down_sync(0xFFFFFFFFu, contrib, off);
        msum    += __shfl_down_sync(0xFFFFFFFFu, msum, off);
    }

    const int lane = tid & 31;
    const int warp = tid >> 5;
    if (warp < 8 && lane == 0) { s_c[warp] = contrib; s_m[warp] = msum; }
    __syncthreads();
    if (warp == 0) {
        float bc = (lane < 8) ? s_c[lane] : 0.0f;
        float bm = (lane < 8) ? s_m[lane] : 0.0f;
        #pragma unroll
        for (int off = 4; off > 0; off >>= 1) {
            bc += __shfl_down_sync(0xFFFFFFFFu, bc, off);
            bm += __shfl_down_sync(0xFFFFFFFFu, bm, off);
        }
        if (lane == 0) {
            atomicAdd(&g_acc[0], bc);
            atomicAdd(&g_acc[1], bm);
            __threadfence();
            const unsigned old = atomicAdd(&g_count, 1u);
            s_last = (old == (unsigned)(gridDim.x - 1));
        }
    }
    __syncthreads();

    // Last block: produce output and reset state for the next replay.
    if (s_last && tid == 0) {
        out[0] = g_acc[0] / g_acc[1];
        g_acc[0] = 0.0f;
        g_acc[1] = 0.0f;
        g_count  = 0u;
    }
}

extern "C" void kernel_launch(void* const* d_in, const int* in_sizes, int n_in,
                              void* d_out, int out_size) {
    const float* u    = (const float*)d_in[0];  // unmasked_latent_tensors [B,C,H,W]
    const float* m    = (const float*)d_in[1];  // masked_latent_tensors   [B,C,H,W]
    const int*   mask = (const int*)d_in[2];    // latent_mask [B,H,W]
    float* out = (float*)d_out;

    cms_tma_kernel<<<NCTAS_, THREADS_>>>(u, m, mask, out);
}

// round 8
// speedup vs baseline: 1.1348x; 1.0499x over previous
#include <cuda_runtime.h>
#include <math.h>
#include <cstdint>

// Problem constants (fixed shapes from reference)
#define B_    32
#define C_    256
#define HW_   4096
#define BHW_  131072
#define EPS_  1e-8f

#define POS_PER_CTA_  128
#define NCTAS_        (BHW_ / POS_PER_CTA_)   // 1024
#define CTAS_PER_IMG_ (HW_ / POS_PER_CTA_)    // 32
#define NSTAGES_      8
#define CH_PER_STAGE_ 2
#define NCHUNKS_      (C_ / CH_PER_STAGE_)    // 128 stage-iterations
#define NCONS_        64                      // consumer threads (2 warps)
#define THREADS_      96                      // +1 producer warp
#define CH_BYTES_     (POS_PER_CTA_ * 4)      // 512 B per tensor per channel
#define STAGE_TX_     (2 * CH_PER_STAGE_ * CH_BYTES_)  // 2048 B per stage

// Scratch accumulators: [0] = sum(sim*mask), [1] = sum(mask).
// Zero-initialized at module load; the finalizing block resets them after
// each use so every graph replay sees identical initial state.
__device__ float    g_acc[2];
__device__ unsigned g_count;

__device__ __forceinline__ uint32_t smem_u32(const void* p) {
    uint32_t a;
    asm("{ .reg .u64 t; cvta.to.shared.u64 t, %1; cvt.u32.u64 %0, t; }"
        : "=r"(a) : "l"(p));
    return a;
}
__device__ __forceinline__ void mbar_init(uint32_t m, uint32_t cnt) {
    asm volatile("mbarrier.init.shared.b64 [%0], %1;" :: "r"(m), "r"(cnt) : "memory");
}
__device__ __forceinline__ void mbar_expect_tx(uint32_t m, uint32_t tx) {
    asm volatile("mbarrier.arrive.expect_tx.shared.b64 _, [%0], %1;"
                 :: "r"(m), "r"(tx) : "memory");
}
__device__ __forceinline__ void mbar_arrive(uint32_t m) {
    asm volatile("mbarrier.arrive.shared.b64 _, [%0];" :: "r"(m) : "memory");
}
__device__ __forceinline__ void mbar_wait(uint32_t m, uint32_t parity) {
    asm volatile(
        "{\n\t"
        ".reg .pred P;\n\t"
        "WL_%=:\n\t"
        "mbarrier.try_wait.parity.acquire.cta.shared::cta.b64 P, [%0], %1, 0x989680;\n\t"
        "@P bra.uni WD_%=;\n\t"
        "bra.uni WL_%=;\n\t"
        "WD_%=:\n\t"
        "}"
        :: "r"(m), "r"(parity) : "memory");
}
__device__ __forceinline__ void bulk_g2s(uint32_t dst, const void* src,
                                         uint32_t bytes, uint32_t mbar) {
    asm volatile(
        "cp.async.bulk.shared::cta.global.mbarrier::complete_tx::bytes "
        "[%0], [%1], %2, [%3];"
        :: "r"(dst), "l"(src), "r"(bytes), "r"(mbar) : "memory");
}

__global__ __launch_bounds__(THREADS_)
void cms_tma_kernel(const float* __restrict__ u,
                    const float* __restrict__ m,
                    const int*   __restrict__ mask,
                    float*       __restrict__ out) {
    // Stage layout: [stage][channel-in-stage][position]
    __shared__ alignas(128) float su[NSTAGES_][CH_PER_STAGE_][POS_PER_CTA_]; // 8 KB
    __shared__ alignas(128) float sv[NSTAGES_][CH_PER_STAGE_][POS_PER_CTA_]; // 8 KB
    __shared__ alignas(8)  unsigned long long bar_full[NSTAGES_];
    __shared__ alignas(8)  unsigned long long bar_empty[NSTAGES_];
    __shared__ float s_c[2], s_m[2];
    __shared__ bool  s_last;

    const int tid = threadIdx.x;
    const int cta = blockIdx.x;
    const int b   = cta >> 5;                           // 32 CTAs per image
    const int hw0 = (cta & (CTAS_PER_IMG_ - 1)) * POS_PER_CTA_;

    const uint32_t full0  = smem_u32(&bar_full[0]);
    const uint32_t empty0 = smem_u32(&bar_empty[0]);

    if (tid == 0) {
        #pragma unroll
        for (int s = 0; s < NSTAGES_; ++s) {
            mbar_init(full0  + 8u * s, 1);       // producer's expect_tx arrive
            mbar_init(empty0 + 8u * s, NCONS_);  // all consumers arrive
        }
    }
    __syncthreads();

    float contrib = 0.0f, msum = 0.0f;

    if (tid >= NCONS_) {
        // ---------------- producer (single thread of warp 2) ----------------
        if (tid == NCONS_) {
            const char* gu = (const char*)(u + (size_t)b * C_ * HW_ + hw0);
            const char* gm = (const char*)(m + (size_t)b * C_ * HW_ + hw0);
            const uint32_t du = smem_u32(&su[0][0][0]);
            const uint32_t dv = smem_u32(&sv[0][0][0]);
            int st = 0, ph = 1;   // phase 1: first NSTAGES_ empty-waits pass immediately
            for (int k = 0; k < NCHUNKS_; ++k) {
                const uint32_t fb = full0 + 8u * st;
                mbar_wait(empty0 + 8u * st, (uint32_t)ph);
                mbar_expect_tx(fb, STAGE_TX_);
                const size_t goff0 = (size_t)(2 * k)     * HW_ * 4;
                const size_t goff1 = (size_t)(2 * k + 1) * HW_ * 4;
                const uint32_t soff = (uint32_t)st * (CH_PER_STAGE_ * CH_BYTES_);
                bulk_g2s(du + soff,             gu + goff0, CH_BYTES_, fb);
                bulk_g2s(du + soff + CH_BYTES_, gu + goff1, CH_BYTES_, fb);
                bulk_g2s(dv + soff,             gm + goff0, CH_BYTES_, fb);
                bulk_g2s(dv + soff + CH_BYTES_, gm + goff1, CH_BYTES_, fb);
                if (++st == NSTAGES_) { st = 0; ph ^= 1; }
            }
        }
    } else {
        // -------- consumers: thread t owns positions hw0+2t, hw0+2t+1 --------
        float dot0 = 0.0f, uu0 = 0.0f, mm0 = 0.0f;
        float dot1 = 0.0f, uu1 = 0.0f, mm1 = 0.0f;
        int st = 0, ph = 0;
        for (int k = 0; k < NCHUNKS_; ++k) {
            mbar_wait(full0 + 8u * st, (uint32_t)ph);
            #pragma unroll
            for (int ch = 0; ch < CH_PER_STAGE_; ++ch) {
                const float2 a = ((const float2*)&su[st][ch][0])[tid];
                const float2 x = ((const float2*)&sv[st][ch][0])[tid];
                dot0 = fmaf(a.x, x.x, dot0);
                uu0  = fmaf(a.x, a.x, uu0);
                mm0  = fmaf(x.x, x.x, mm0);
                dot1 = fmaf(a.y, x.y, dot1);
                uu1  = fmaf(a.y, a.y, uu1);
                mm1  = fmaf(x.y, x.y, mm1);
            }
            mbar_arrive(empty0 + 8u * st);
            if (++st == NSTAGES_) { st = 0; ph ^= 1; }
        }

        const int pos = b * HW_ + hw0 + 2 * tid;
        const int2 mk = *(const int2*)(mask + pos);
        const float mf0 = (mk.x != 0) ? 1.0f : 0.0f;
        const float mf1 = (mk.y != 0) ? 1.0f : 0.0f;
        const float d0 = fmaxf(sqrtf(uu0), EPS_) * fmaxf(sqrtf(mm0), EPS_);
        const float d1 = fmaxf(sqrtf(uu1), EPS_) * fmaxf(sqrtf(mm1), EPS_);
        contrib = (dot0 / d0) * mf0 + (dot1 / d1) * mf1;
        msum    = mf0 + mf1;
    }

    // Warp reduction (producer warp contributes zeros)
    #pragma unroll
    for (int off = 16; off > 0; off >>= 1) {
        contrib += __shfl_down_sync(0xFFFFFFFFu, contrib, off);
        msum    += __shfl_down_sync(0xFFFFFFFFu, msum, off);
    }

    const int lane = tid & 31;
    const int warp = tid >> 5;
    if (warp < 2 && lane == 0) { s_c[warp] = contrib; s_m[warp] = msum; }
    __syncthreads();
    if (tid == 0) {
        const float bc = s_c[0] + s_c[1];
        const float bm = s_m[0] + s_m[1];
        atomicAdd(&g_acc[0], bc);
        atomicAdd(&g_acc[1], bm);
        __threadfence();
        const unsigned old = atomicAdd(&g_count, 1u);
        s_last = (old == (unsigned)(gridDim.x - 1));
    }
    __syncthreads();

    // Last block: produce output and reset state for the next replay.
    if (s_last && tid == 0) {
        out[0] = g_acc[0] / g_acc[1];
        g_acc[0] = 0.0f;
        g_acc[1] = 0.0f;
        g_count  = 0u;
    }
}

extern "C" void kernel_launch(void* const* d_in, const int* in_sizes, int n_in,
                              void* d_out, int out_size) {
    const float* u    = (const float*)d_in[0];  // unmasked_latent_tensors [B,C,H,W]
    const float* m    = (const float*)d_in[1];  // masked_latent_tensors   [B,C,H,W]
    const int*   mask = (const int*)d_in[2];    // latent_mask [B,H,W]
    float* out = (float*)d_out;

    cms_tma_kernel<<<NCTAS_, THREADS_>>>(u, m, mask, out);
}